// round 1
// baseline (speedup 1.0000x reference)
#include <cuda_runtime.h>
#include <math.h>

// Problem constants (fixed by the dataset)
#define DD   128      // d_model
#define HH   8        // heads
#define CC   16       // channels per head
#define EDIM 16       // edge feature dim
#define NMAX 50000
#define EMAX 800000

#define FULLMASK 0xffffffffu

// ---------------- scratch (static device globals; no allocation) ----------------
__device__ float g_xl[NMAX * DD];        // 25.6 MB
__device__ float g_xr[NMAX * DD];        // 25.6 MB
__device__ float g_score[EMAX * HH];     // 25.6 MB (scores, then overwritten with exp)
__device__ int   g_deg[NMAX];
__device__ int   g_cnt[NMAX];
__device__ int   g_off[NMAX + 1];
__device__ int   g_perm[EMAX];
__device__ float g_sum[DD];
__device__ float g_sumsq[DD];
__device__ float g_scale[DD];
__device__ float g_shift[DD];

// ---------------- init ----------------
__global__ void k_zero(int n) {
    int i = blockIdx.x * blockDim.x + threadIdx.x;
    int stride = gridDim.x * blockDim.x;
    for (int j = i; j < n; j += stride) { g_deg[j] = 0; g_cnt[j] = 0; }
    if (i < DD) { g_sum[i] = 0.f; g_sumsq[i] = 0.f; }
}

// ---------------- node transform: h = emb[x]*sqrt(D); xl = h@Wl+bl; xr = h@Wr+br --------
// 256 threads: col = tid&127 (one output column), rt = tid>>7 selects 8-row half of a
// 16-row batch. W read through L1 (__ldg, 128KB resident), h staged in smem (broadcast LDS).
__global__ __launch_bounds__(256) void k_node(
    const int* __restrict__ x, const float* __restrict__ emb,
    const float* __restrict__ Wl, const float* __restrict__ bl,
    const float* __restrict__ Wr, const float* __restrict__ br,
    int n, int rpb)
{
    __shared__ float hs[16 * DD];
    int tid = threadIdx.x;
    int col = tid & 127;
    int rt  = tid >> 7;  // 0 or 1
    int r0 = blockIdx.x * rpb;
    int r1 = min(n, r0 + rpb);
    if (r0 >= r1) return;
    float mybl = __ldg(bl + col);
    float mybr = __ldg(br + col);
    const float SQ = 11.313708498984761f;  // sqrt(128)

    for (int base = r0; base < r1; base += 16) {
        int nrows = min(16, r1 - base);
        // stage 16 rows of h (coalesced)
        for (int i = tid; i < 16 * DD; i += 256) {
            int r = i >> 7, c = i & 127;
            float v = 0.f;
            if (r < nrows) v = __ldg(emb + x[base + r] * DD + c) * SQ;
            hs[i] = v;
        }
        __syncthreads();

        float accl[8], accr[8];
        #pragma unroll
        for (int r = 0; r < 8; r++) { accl[r] = mybl; accr[r] = mybr; }

        const float* hrow = hs + rt * 8 * DD;
        #pragma unroll 4
        for (int k = 0; k < DD; k++) {
            float wl = __ldg(Wl + k * DD + col);
            float wr = __ldg(Wr + k * DD + col);
            #pragma unroll
            for (int r = 0; r < 8; r++) {
                float hv = hrow[r * DD + k];   // smem broadcast within warp
                accl[r] = fmaf(hv, wl, accl[r]);
                accr[r] = fmaf(hv, wr, accr[r]);
            }
        }
        #pragma unroll
        for (int r = 0; r < 8; r++) {
            int row = base + rt * 8 + r;
            if (row < r1) {
                g_xl[row * DD + col] = accl[r];
                g_xr[row * DD + col] = accr[r];
            }
        }
        __syncthreads();
    }
}

// ---------------- CSR build ----------------
__global__ void k_hist(const int* __restrict__ ei, int E) {
    int e = blockIdx.x * blockDim.x + threadIdx.x;
    if (e < E) atomicAdd(&g_deg[ei[E + e]], 1);
}

__global__ __launch_bounds__(1024) void k_scan(int n) {
    __shared__ int wsum[32];
    int tid = threadIdx.x;
    int per = (n + 1023) >> 10;
    int t0 = tid * per;
    int s = 0;
    for (int i = 0; i < per; i++) {
        int idx = t0 + i;
        if (idx < n) s += g_deg[idx];
    }
    int lane = tid & 31, wid = tid >> 5;
    // inclusive warp scan
    int v = s;
    #pragma unroll
    for (int o = 1; o < 32; o <<= 1) {
        int t = __shfl_up_sync(FULLMASK, v, o);
        if (lane >= o) v += t;
    }
    if (lane == 31) wsum[wid] = v;
    __syncthreads();
    if (wid == 0) {
        int w = wsum[lane];
        #pragma unroll
        for (int o = 1; o < 32; o <<= 1) {
            int t = __shfl_up_sync(FULLMASK, w, o);
            if (lane >= o) w += t;
        }
        wsum[lane] = w;
    }
    __syncthreads();
    int excl = v - s + (wid > 0 ? wsum[wid - 1] : 0);
    int run = excl;
    for (int i = 0; i < per; i++) {
        int idx = t0 + i;
        if (idx < n) { g_off[idx] = run; run += g_deg[idx]; }
    }
    if (tid == 1023) g_off[n] = run;   // last thread's range is past n -> run == total
}

__global__ void k_scatter(const int* __restrict__ ei, int E) {
    int e = blockIdx.x * blockDim.x + threadIdx.x;
    if (e < E) {
        int dst = ei[E + e];
        int pos = g_off[dst] + atomicAdd(&g_cnt[dst], 1);
        g_perm[pos] = e;
    }
}

// ---------------- edge attention scores --------------------------------------
// warp per 4-edge group. lane owns 4 channels (ch = lane*4). W_e and att in smem.
__global__ __launch_bounds__(256) void k_score(
    const int* __restrict__ ei, const float* __restrict__ ew,
    const float* __restrict__ We, const float* __restrict__ att, int E)
{
    __shared__ float sWe[EDIM * DD];   // 8 KB
    __shared__ float satt[DD];
    int tid = threadIdx.x;
    for (int i = tid; i < EDIM * DD / 4; i += 256)
        ((float4*)sWe)[i] = ((const float4*)We)[i];
    if (tid < DD) satt[tid] = att[tid];
    __syncthreads();

    int lane = tid & 31;
    int wid  = tid >> 5;
    int gw = blockIdx.x * 8 + wid;
    int nw = gridDim.x * 8;
    int ngroups = (E + 3) >> 2;
    float4 a4 = ((float4*)satt)[lane];

    for (int g = gw; g < ngroups; g += nw) {
        int e0 = g * 4;
        float4 xlv[4], xrv[4], ee[4];
        float ewv[4];
        #pragma unroll
        for (int j = 0; j < 4; j++) {
            int e = e0 + j;
            ee[j] = make_float4(0.f, 0.f, 0.f, 0.f);
            if (e < E) {
                int src = ei[e];
                int dst = ei[E + e];
                xlv[j] = *(const float4*)(g_xl + src * DD + lane * 4);
                xrv[j] = *(const float4*)(g_xr + dst * DD + lane * 4);
                ewv[j] = (lane < EDIM) ? __ldg(ew + e * EDIM + lane) : 0.f;
            } else {
                xlv[j] = make_float4(0.f, 0.f, 0.f, 0.f);
                xrv[j] = xlv[j];
                ewv[j] = 0.f;
            }
        }
        #pragma unroll
        for (int d = 0; d < EDIM; d++) {
            float4 w4 = ((float4*)sWe)[d * 32 + lane];
            #pragma unroll
            for (int j = 0; j < 4; j++) {
                float wd = __shfl_sync(FULLMASK, ewv[j], d);
                ee[j].x = fmaf(wd, w4.x, ee[j].x);
                ee[j].y = fmaf(wd, w4.y, ee[j].y);
                ee[j].z = fmaf(wd, w4.z, ee[j].z);
                ee[j].w = fmaf(wd, w4.w, ee[j].w);
            }
        }
        #pragma unroll
        for (int j = 0; j < 4; j++) {
            float mx = xlv[j].x + xrv[j].x + ee[j].x;
            float my = xlv[j].y + xrv[j].y + ee[j].y;
            float mz = xlv[j].z + xrv[j].z + ee[j].z;
            float mw = xlv[j].w + xrv[j].w + ee[j].w;
            mx = mx > 0.f ? mx : 0.2f * mx;
            my = my > 0.f ? my : 0.2f * my;
            mz = mz > 0.f ? mz : 0.2f * mz;
            mw = mw > 0.f ? mw : 0.2f * mw;
            float p = mx * a4.x + my * a4.y + mz * a4.z + mw * a4.w;
            p += __shfl_xor_sync(FULLMASK, p, 1);
            p += __shfl_xor_sync(FULLMASK, p, 2);
            int e = e0 + j;
            if (e < E && (lane & 3) == 0)
                g_score[e * HH + (lane >> 2)] = p;
        }
    }
}

// ---------------- warp-per-node softmax + aggregation (no float atomics) ------
__global__ __launch_bounds__(256) void k_agg(
    const int* __restrict__ ei, const float* __restrict__ bias,
    float* __restrict__ out, int n)
{
    int lane = threadIdx.x & 31;
    int wid  = threadIdx.x >> 5;
    int v = blockIdx.x * 8 + wid;
    if (v >= n) return;
    int start = g_off[v];
    int end   = g_off[v + 1];

    int h8 = lane & 7, sub = lane >> 3;   // 8 heads x 4 sub-lanes
    // pass 1: per-head max
    float mx = -3.0e38f;
    for (int i = start + sub; i < end; i += 4) {
        int e = g_perm[i];
        mx = fmaxf(mx, g_score[e * HH + h8]);
    }
    mx = fmaxf(mx, __shfl_xor_sync(FULLMASK, mx, 8));
    mx = fmaxf(mx, __shfl_xor_sync(FULLMASK, mx, 16));

    // pass 2: exp in place + denominator
    float ds = 0.f;
    for (int i = start + sub; i < end; i += 4) {
        int e = g_perm[i];
        float exv = __expf(g_score[e * HH + h8] - mx);
        g_score[e * HH + h8] = exv;
        ds += exv;
    }
    ds += __shfl_xor_sync(FULLMASK, ds, 8);
    ds += __shfl_xor_sync(FULLMASK, ds, 16);

    int myh = lane >> 2;                       // head for my 4 channels
    float den = __shfl_sync(FULLMASK, ds, myh); // lane 'myh' holds head myh's denom
    float invd = (end > start) ? 1.f / den : 0.f;

    // pass 3: weighted gather-accumulate
    float4 acc = make_float4(0.f, 0.f, 0.f, 0.f);
    for (int i = start; i < end; i++) {
        int e = g_perm[i];
        int src = ei[e];
        float w = g_score[e * HH + myh] * invd;
        float4 xv = *(const float4*)(g_xl + src * DD + lane * 4);
        acc.x = fmaf(w, xv.x, acc.x);
        acc.y = fmaf(w, xv.y, acc.y);
        acc.z = fmaf(w, xv.z, acc.z);
        acc.w = fmaf(w, xv.w, acc.w);
    }
    float4 b4 = ((const float4*)bias)[lane];
    acc.x += b4.x; acc.y += b4.y; acc.z += b4.z; acc.w += b4.w;
    *(float4*)(out + v * DD + lane * 4) = acc;
}

// ---------------- BatchNorm statistics ----------------
__global__ __launch_bounds__(256) void k_stats(const float* __restrict__ out, int n) {
    __shared__ float ssum[256], ssq[256];
    int tid = threadIdx.x;
    int ch = tid & 127;
    int half = tid >> 7;
    float s = 0.f, q = 0.f;
    int stride = gridDim.x * 2;
    for (int r = blockIdx.x * 2 + half; r < n; r += stride) {
        float vv = out[r * DD + ch];
        s += vv;
        q = fmaf(vv, vv, q);
    }
    ssum[tid] = s; ssq[tid] = q;
    __syncthreads();
    if (tid < 128) {
        atomicAdd(&g_sum[ch],   ssum[tid] + ssum[tid + 128]);
        atomicAdd(&g_sumsq[ch], ssq[tid]  + ssq[tid + 128]);
    }
}

__global__ void k_finalize(const float* __restrict__ gamma, const float* __restrict__ beta, int n) {
    int t = threadIdx.x;
    if (t < DD) {
        float invn = 1.f / (float)n;
        float mean = g_sum[t] * invn;
        float var  = g_sumsq[t] * invn - mean * mean;
        if (var < 0.f) var = 0.f;
        float inv = rsqrtf(var + 1e-5f);
        float sc = gamma[t] * inv;
        g_scale[t] = sc;
        g_shift[t] = beta[t] - mean * sc;
    }
}

__global__ void k_apply(float* __restrict__ out, int n) {
    int i = blockIdx.x * blockDim.x + threadIdx.x;
    int total = n * (DD / 4);
    if (i < total) {
        float4 v = ((float4*)out)[i];
        float4 sc = ((float4*)g_scale)[i & 31];
        float4 sh = ((float4*)g_shift)[i & 31];
        float yx = fmaf(v.x, sc.x, sh.x);
        float yy = fmaf(v.y, sc.y, sh.y);
        float yz = fmaf(v.z, sc.z, sh.z);
        float yw = fmaf(v.w, sc.w, sh.w);
        v.x = yx > 0.f ? yx : 0.01f * yx;
        v.y = yy > 0.f ? yy : 0.01f * yy;
        v.z = yz > 0.f ? yz : 0.01f * yz;
        v.w = yw > 0.f ? yw : 0.01f * yw;
        ((float4*)out)[i] = v;
    }
}

// ---------------- launch ----------------
extern "C" void kernel_launch(void* const* d_in, const int* in_sizes, int n_in,
                              void* d_out, int out_size)
{
    const int*   x     = (const int*)  d_in[0];
    const int*   ei    = (const int*)  d_in[1];
    const float* ew    = (const float*)d_in[2];
    const float* emb   = (const float*)d_in[3];
    const float* Wl    = (const float*)d_in[4];
    const float* bl    = (const float*)d_in[5];
    const float* Wr    = (const float*)d_in[6];
    const float* br    = (const float*)d_in[7];
    const float* att   = (const float*)d_in[8];
    const float* We    = (const float*)d_in[9];
    const float* bias  = (const float*)d_in[10];
    const float* gamma = (const float*)d_in[11];
    const float* beta  = (const float*)d_in[12];
    float* out = (float*)d_out;

    int n = in_sizes[0];
    int E = in_sizes[1] / 2;

    k_zero<<<64, 256>>>(n);

    int rpb = (n + 147) / 148;
    k_node<<<148, 256>>>(x, emb, Wl, bl, Wr, br, n, rpb);

    k_hist<<<(E + 255) / 256, 256>>>(ei, E);
    k_scan<<<1, 1024>>>(n);
    k_scatter<<<(E + 255) / 256, 256>>>(ei, E);

    k_score<<<1184, 256>>>(ei, ew, We, att, E);

    k_agg<<<(n + 7) / 8, 256>>>(ei, bias, out, n);

    k_stats<<<128, 256>>>(out, n);
    k_finalize<<<1, 128>>>(gamma, beta, n);
    k_apply<<<(n * (DD / 4) + 255) / 256, 256>>>(out, n);
}